// round 16
// baseline (speedup 1.0000x reference)
#include <cuda_runtime.h>

#define NV   2000000
#define NC   2000
#define NE   16000
#define NREP 8         // replicas per cluster, padded to 32B stride
#define GRID 296       // 2 CTAs/SM x 148 SMs: all blocks co-resident
#define TPB  256
#define NG   (NV / 4)  // 500000 groups of 4 voxels
#define NG_S 175104    // ~35% of groups -> smem ATOMS pipe; rest -> REDG pipe

// Scratch (no cudaMalloc allowed).
// Replica r of cluster c at float4 index c*16 + r*2 (32B apart: own L2 sector).
__device__ float4       g_rsum[NC * NREP * 2];   // 512 KB
__device__ unsigned int g_icnt[NC];
// Monotonic grid-barrier counters (never reset; grow by GRID per launch).
__device__ unsigned int g_bar0, g_bar1;

__device__ __forceinline__ void red_v4(float4* a, float x, float y, float z, float w) {
    asm volatile("red.global.add.v4.f32 [%0], {%1,%2,%3,%4};"
                 :: "l"(a), "f"(x), "f"(y), "f"(z), "f"(w) : "memory");
}
__device__ __forceinline__ void red_u32(unsigned int* a, unsigned int v) {
    asm volatile("red.global.add.u32 [%0], %1;" :: "l"(a), "r"(v) : "memory");
}
__device__ __forceinline__ unsigned long long pack2(float a, float b) {
    unsigned long long r;
    asm("mov.b64 %0, {%1, %2};" : "=l"(r) : "f"(a), "f"(b));
    return r;
}
__device__ __forceinline__ void unpack2(unsigned long long v, float& a, float& b) {
    asm("mov.b64 {%0, %1}, %2;" : "=f"(a), "=f"(b) : "l"(v));
}
__device__ __forceinline__ void ffma2(unsigned long long& d,
                                      unsigned long long a, unsigned long long b) {
    asm("fma.rn.f32x2 %0, %1, %2, %0;" : "+l"(d) : "l"(a), "l"(b));
}

// Software grid barrier: monotonic counter, wrap-free across graph replays.
__device__ __forceinline__ void grid_barrier(unsigned int* ctr) {
    __syncthreads();
    if (threadIdx.x == 0) {
        __threadfence();
        unsigned int t = atomicAdd(ctr, 1u);
        unsigned int target = (t / GRID + 1u) * GRID;
        unsigned int v;
        do {
            asm volatile("ld.acquire.gpu.u32 %0, [%1];" : "=r"(v) : "l"(ctr));
        } while (v < target);
        __threadfence();
    }
    __syncthreads();
}

// ---------------------------------------------------------------------------
// ONE fused kernel, 296 x 256.
// Phase 1 is WARP-SPECIALIZED across two independent atomic pipes:
//   warps 0-2: ~35% of voxels -> smem float bins (SM-local ATOMS pipe)
//   warps 3-7: ~65% of voxels -> red.v4 padded replicas (LTS REDG pipe)
// Both pipes run concurrently; bins flush once per block as 500 red.v4.
// smem floats: W2 [0,8192) | union{ phase1: fsum 8000 + cnt 2000 ;
//                                   phase2: h 8192 + misc 1024 } [8192,18432)
// ---------------------------------------------------------------------------
__global__ __launch_bounds__(TPB) void k_fused(const float* __restrict__ data,
                                               const int*   __restrict__ cid,
                                               const int*   __restrict__ eidx,
                                               const float* __restrict__ W1,
                                               const float* __restrict__ b1,
                                               const float* __restrict__ W2,
                                               const float* __restrict__ b2,
                                               float*       __restrict__ out) {
    extern __shared__ float sm[];
    float* s_W2 = sm;                          // 8192 floats [128][64]
    float* s_u  = sm + 8192;                   // union region (10240 floats)

    const int t   = threadIdx.x;
    const int bid = blockIdx.x;

    // ---- Phase 0: zero accumulators; preload W2; zero smem bins ----
    for (int i = bid * TPB + t; i < NC * NREP * 2; i += GRID * TPB)
        g_rsum[i] = make_float4(0.f, 0.f, 0.f, 0.f);
    for (int i = bid * TPB + t; i < NC; i += GRID * TPB)
        g_icnt[i] = 0u;
    for (int i = t; i < 8192 / 4; i += TPB)
        ((float4*)s_W2)[i] = ((const float4*)W2)[i];
    float*        s_fsum = s_u;                        // NC*4 floats (32KB)
    unsigned int* s_cnt  = (unsigned int*)(s_u + NC * 4); // NC uints (8KB)
    for (int i = t; i < NC * 4; i += TPB) s_fsum[i] = 0.f;
    for (int i = t; i < NC;     i += TPB) s_cnt[i] = 0u;

    grid_barrier(&g_bar0);

    // ---- Phase 1: dual-pipe segment sum ----
    if (t < 96) {
        // smem ATOMS pipe: warps 0..2, groups [0, NG_S)
        for (int g = bid * 96 + t; g < NG_S; g += GRID * 96) {
            const float4* p = (const float4*)data + (size_t)g * 5;
            float4 q0 = __ldg(p + 0);
            float4 q1 = __ldg(p + 1);
            float4 q2 = __ldg(p + 2);
            float4 q3 = __ldg(p + 3);
            float4 q4 = __ldg(p + 4);
            int4 c = __ldg((const int4*)cid + g);

            atomicAdd(&s_fsum[c.x * 4 + 0], q0.y);
            atomicAdd(&s_fsum[c.x * 4 + 1], q0.z);
            atomicAdd(&s_fsum[c.x * 4 + 2], q0.w);
            atomicAdd(&s_fsum[c.x * 4 + 3], q1.x);
            atomicAdd(&s_cnt[c.x], 1u);
            atomicAdd(&s_fsum[c.y * 4 + 0], q1.z);
            atomicAdd(&s_fsum[c.y * 4 + 1], q1.w);
            atomicAdd(&s_fsum[c.y * 4 + 2], q2.x);
            atomicAdd(&s_fsum[c.y * 4 + 3], q2.y);
            atomicAdd(&s_cnt[c.y], 1u);
            atomicAdd(&s_fsum[c.z * 4 + 0], q2.w);
            atomicAdd(&s_fsum[c.z * 4 + 1], q3.x);
            atomicAdd(&s_fsum[c.z * 4 + 2], q3.y);
            atomicAdd(&s_fsum[c.z * 4 + 3], q3.z);
            atomicAdd(&s_cnt[c.z], 1u);
            atomicAdd(&s_fsum[c.w * 4 + 0], q4.x);
            atomicAdd(&s_fsum[c.w * 4 + 1], q4.y);
            atomicAdd(&s_fsum[c.w * 4 + 2], q4.z);
            atomicAdd(&s_fsum[c.w * 4 + 3], q4.w);
            atomicAdd(&s_cnt[c.w], 1u);
        }
    } else {
        // REDG pipe: warps 3..7, groups [NG_S, NG)
        const int rep2 = ((bid * 8 + (t >> 5)) & (NREP - 1)) * 2;
        const int tt = t - 96;
#pragma unroll 2
        for (int g = NG_S + bid * 160 + tt; g < NG; g += GRID * 160) {
            const float4* p = (const float4*)data + (size_t)g * 5;
            float4 q0 = __ldg(p + 0);
            float4 q1 = __ldg(p + 1);
            float4 q2 = __ldg(p + 2);
            float4 q3 = __ldg(p + 3);
            float4 q4 = __ldg(p + 4);
            int4 c = __ldg((const int4*)cid + g);

            red_v4(&g_rsum[c.x * (NREP * 2) + rep2], q0.y, q0.z, q0.w, q1.x);
            red_v4(&g_rsum[c.y * (NREP * 2) + rep2], q1.z, q1.w, q2.x, q2.y);
            red_v4(&g_rsum[c.z * (NREP * 2) + rep2], q2.w, q3.x, q3.y, q3.z);
            red_v4(&g_rsum[c.w * (NREP * 2) + rep2], q4.x, q4.y, q4.z, q4.w);

            atomicAdd(&s_cnt[c.x], 1u);
            atomicAdd(&s_cnt[c.y], 1u);
            atomicAdd(&s_cnt[c.z], 1u);
            atomicAdd(&s_cnt[c.w], 1u);
        }
    }
    __syncthreads();

    // Flush bins: one red.v4 per cluster into replica 0; counts via red.u32.
    for (int i = t; i < NC; i += TPB) {
        float4 v = ((const float4*)s_fsum)[i];
        if (v.x != 0.f || v.y != 0.f || v.z != 0.f || v.w != 0.f)
            red_v4(&g_rsum[i * (NREP * 2)], v.x, v.y, v.z, v.w);
        unsigned int u = s_cnt[i];
        if (u) red_u32(&g_icnt[i], u);
    }

    grid_barrier(&g_bar1);

    // ---- Phase 2: edge MLP on blocks 0..249 (64 edges each) ----
    if (bid >= NE / 64) return;

    float* s_h    = s_u;             // 8192 floats [128][64] (bins are dead)
    float* s_misc = s_u + 8192;      // 1024 floats
    float* s_W1   = s_misc;          // 512 floats [4][128]
    float* s_b1   = s_misc + 512;    // 128
    float* s_b2   = s_misc + 640;    // 64
    float* s_pool = s_misc + 704;    // 320 floats [64][5]

    __syncthreads();
    if (t < 128) ((float4*)s_W1)[t] = ((const float4*)W1)[t];
    if (t < 128) s_b1[t] = b1[t];
    if (t < 64)  s_b2[t] = b2[t];

    const int base = bid * 64;

    // Gather: 4 threads/edge, each sums 2 padded replicas of both endpoints
    // (4 pipelined LDG.128 from warm L2), 2-step shfl reduce.
    {
        int q = t & 3;
        int e = t >> 2;
        int eg = base + e;
        int a = __ldg(eidx + eg);
        int b = __ldg(eidx + NE + eg);

        const float4* ra = g_rsum + a * (NREP * 2) + q * 4;
        const float4* rb = g_rsum + b * (NREP * 2) + q * 4;
        float4 va0 = __ldg(ra + 0);
        float4 va1 = __ldg(ra + 2);
        float4 vb0 = __ldg(rb + 0);
        float4 vb1 = __ldg(rb + 2);
        float4 s = make_float4(va0.x + va1.x + vb0.x + vb1.x,
                               va0.y + va1.y + vb0.y + vb1.y,
                               va0.z + va1.z + vb0.z + vb1.z,
                               va0.w + va1.w + vb0.w + vb1.w);
#pragma unroll
        for (int off = 2; off > 0; off >>= 1) {
            s.x += __shfl_down_sync(0xffffffff, s.x, off);
            s.y += __shfl_down_sync(0xffffffff, s.y, off);
            s.z += __shfl_down_sync(0xffffffff, s.z, off);
            s.w += __shfl_down_sync(0xffffffff, s.w, off);
        }
        if (q == 0) {
            float cnt = (float)(__ldg(g_icnt + a) + __ldg(g_icnt + b));
            float inv = 1.f / fmaxf(cnt, 1.f);
            s_pool[e * 5 + 0] = s.x * inv;
            s_pool[e * 5 + 1] = s.y * inv;
            s_pool[e * 5 + 2] = s.z * inv;
            s_pool[e * 5 + 3] = s.w * inv;
        }
    }
    __syncthreads();

    // Phase A: e = t&63, k-group kq = (t>>6)*32.
    {
        int e  = t & 63;
        int kq = (t >> 6) * 32;
        float p0 = s_pool[e * 5 + 0];
        float p1 = s_pool[e * 5 + 1];
        float p2 = s_pool[e * 5 + 2];
        float p3 = s_pool[e * 5 + 3];
#pragma unroll 4
        for (int j = 0; j < 32; j++) {
            int k = kq + j;
            float h = s_b1[k]
                    + p0 * s_W1[0 * 128 + k]
                    + p1 * s_W1[1 * 128 + k]
                    + p2 * s_W1[2 * 128 + k]
                    + p3 * s_W1[3 * 128 + k];
            s_h[k * 64 + e] = fmaxf(h, 0.f);
        }
    }
    __syncthreads();

    // Phase B: 4 edges x 4 outs per thread, packed f32x2 accumulators.
    const int tx = t & 15;
    const int ty = t >> 4;
    unsigned long long acc[4][2];
#pragma unroll
    for (int i = 0; i < 4; i++) { acc[i][0] = 0ull; acc[i][1] = 0ull; }

    const float4* hf4 = (const float4*)s_h;    // [128][16]
    const float4* wf4 = (const float4*)s_W2;   // [128][16]
#pragma unroll 4
    for (int k = 0; k < 128; k++) {
        float4 w = wf4[k * 16 + tx];
        float4 h = hf4[k * 16 + ty];
        unsigned long long w01 = pack2(w.x, w.y);
        unsigned long long w23 = pack2(w.z, w.w);
        float hv[4] = {h.x, h.y, h.z, h.w};
#pragma unroll
        for (int i = 0; i < 4; i++) {
            unsigned long long hh = pack2(hv[i], hv[i]);
            ffma2(acc[i][0], hh, w01);
            ffma2(acc[i][1], hh, w23);
        }
    }

    float c0 = s_b2[tx * 4 + 0];
    float c1 = s_b2[tx * 4 + 1];
    float c2 = s_b2[tx * 4 + 2];
    float c3 = s_b2[tx * 4 + 3];
#pragma unroll
    for (int i = 0; i < 4; i++) {
        int e = base + ty * 4 + i;
        float a0, a1, a2, a3;
        unpack2(acc[i][0], a0, a1);
        unpack2(acc[i][1], a2, a3);
        float4 o = make_float4(a0 + c0, a1 + c1, a2 + c2, a3 + c3);
        ((float4*)out)[e * 16 + tx] = o;
    }
}

// ---------------------------------------------------------------------------
// Launch: ONE kernel node (graph-capturable)
// ---------------------------------------------------------------------------
extern "C" void kernel_launch(void* const* d_in, const int* in_sizes, int n_in,
                              void* d_out, int out_size) {
    const float* data = (const float*)d_in[0];
    const int*   cid  = (const int*)  d_in[1];
    const int*   eidx = (const int*)  d_in[2];
    const float* W1   = (const float*)d_in[3];
    const float* b1   = (const float*)d_in[4];
    const float* W2   = (const float*)d_in[5];
    const float* b2   = (const float*)d_in[6];
    float*       out  = (float*)d_out;

    cudaFuncSetAttribute(k_fused, cudaFuncAttributeMaxDynamicSharedMemorySize, 73728);

    k_fused<<<GRID, TPB, 73728>>>(data, cid, eidx, W1, b1, W2, b2, out);
}

// round 17
// speedup vs baseline: 1.1647x; 1.1647x over previous
#include <cuda_runtime.h>

#define NV   2000000
#define NC   2000
#define NE   16000
#define NREP 8         // replicas per cluster, padded to 32B stride
#define GRID 296       // 2 CTAs/SM x 148 SMs: all blocks co-resident
#define TPB  256
#define MLPB (NE / 64) // 250 MLP blocks

// Scratch (no cudaMalloc allowed).
// Replica r of cluster c at float4 index c*16 + r*2 (32B apart: own L2 sector).
// INVARIANT: g_rsum/g_icnt are ZERO at kernel entry — zero-initialized at
// module load, and re-zeroed at the END of every launch by the idle blocks.
__device__ float4       g_rsum[NC * NREP * 2];   // 512 KB
__device__ unsigned int g_icnt[NC];
// Monotonic counters (never reset; grow by GRID per launch).
__device__ unsigned int g_bar1, g_arr;

__device__ __forceinline__ void red_v4(float4* a, float x, float y, float z, float w) {
    asm volatile("red.global.add.v4.f32 [%0], {%1,%2,%3,%4};"
                 :: "l"(a), "f"(x), "f"(y), "f"(z), "f"(w) : "memory");
}
__device__ __forceinline__ void red_u32(unsigned int* a, unsigned int v) {
    asm volatile("red.global.add.u32 [%0], %1;" :: "l"(a), "r"(v) : "memory");
}
__device__ __forceinline__ unsigned long long pack2(float a, float b) {
    unsigned long long r;
    asm("mov.b64 %0, {%1, %2};" : "=l"(r) : "f"(a), "f"(b));
    return r;
}
__device__ __forceinline__ void unpack2(unsigned long long v, float& a, float& b) {
    asm("mov.b64 {%0, %1}, %2;" : "=f"(a), "=f"(b) : "l"(v));
}
__device__ __forceinline__ void ffma2(unsigned long long& d,
                                      unsigned long long a, unsigned long long b) {
    asm("fma.rn.f32x2 %0, %1, %2, %0;" : "+l"(d) : "l"(a), "l"(b));
}

// Blocking grid barrier (monotonic, replay-safe). All GRID blocks co-resident.
__device__ __forceinline__ void grid_barrier(unsigned int* ctr) {
    __syncthreads();
    if (threadIdx.x == 0) {
        __threadfence();
        unsigned int t = atomicAdd(ctr, 1u);
        unsigned int target = (t / GRID + 1u) * GRID;
        unsigned int v;
        do {
            asm volatile("ld.acquire.gpu.u32 %0, [%1];" : "=r"(v) : "l"(ctr));
        } while (v < target);
        __threadfence();
    }
    __syncthreads();
}

// ---------------------------------------------------------------------------
// ONE fused kernel, 296 x 256 (R14 core).
// NEW: no phase-0 global zero, no bar0. seg starts immediately (accumulators
// arrive already zeroed). After the MLP gather each block posts a non-blocking
// arrival; the 46 non-MLP blocks wait for all 296 arrivals and then re-zero
// g_rsum/g_icnt for the next launch, overlapping the MLP's Phase A/B.
// smem floats: W2 [0,8192) | h [8192,16384) | misc [16384,18432)
// ---------------------------------------------------------------------------
__global__ __launch_bounds__(TPB) void k_fused(const float* __restrict__ data,
                                               const int*   __restrict__ cid,
                                               const int*   __restrict__ eidx,
                                               const float* __restrict__ W1,
                                               const float* __restrict__ b1,
                                               const float* __restrict__ W2,
                                               const float* __restrict__ b2,
                                               float*       __restrict__ out) {
    extern __shared__ float sm[];
    float* s_W2   = sm;                      // 8192 floats [128][64]
    float* s_h    = sm + 8192;               // 8192 floats [128][64] k-major
    float* s_misc = sm + 16384;              // 2048 floats

    const int t   = threadIdx.x;
    const int bid = blockIdx.x;

    // ---- Phase 0 (block-local only): preload W2; zero smem hist ----
    for (int i = t; i < 8192 / 4; i += TPB)
        ((float4*)s_W2)[i] = ((const float4*)W2)[i];
    unsigned int* s_cnt = (unsigned int*)s_misc;   // 8KB histogram
    for (int i = t; i < NC; i += TPB) s_cnt[i] = 0u;
    __syncthreads();

    // ---- Phase 1: segment sum (accumulators pre-zeroed by prior launch) ----
    {
        const int rep2 = ((bid * 8 + (t >> 5)) & (NREP - 1)) * 2;
        const int NG = NV / 4;
        const int stride = GRID * TPB;
#pragma unroll 2
        for (int g = bid * TPB + t; g < NG; g += stride) {
            const float4* p = (const float4*)data + (size_t)g * 5;
            float4 q0 = __ldg(p + 0);
            float4 q1 = __ldg(p + 1);
            float4 q2 = __ldg(p + 2);
            float4 q3 = __ldg(p + 3);
            float4 q4 = __ldg(p + 4);
            int4 c = __ldg((const int4*)cid + g);

            // voxel layout: [d f0 f1 f2 f3] x4 -> features are cols 1..4
            red_v4(&g_rsum[c.x * (NREP * 2) + rep2], q0.y, q0.z, q0.w, q1.x);
            red_v4(&g_rsum[c.y * (NREP * 2) + rep2], q1.z, q1.w, q2.x, q2.y);
            red_v4(&g_rsum[c.z * (NREP * 2) + rep2], q2.w, q3.x, q3.y, q3.z);
            red_v4(&g_rsum[c.w * (NREP * 2) + rep2], q4.x, q4.y, q4.z, q4.w);

            atomicAdd(&s_cnt[c.x], 1u);
            atomicAdd(&s_cnt[c.y], 1u);
            atomicAdd(&s_cnt[c.z], 1u);
            atomicAdd(&s_cnt[c.w], 1u);
        }
        __syncthreads();
        for (int i = t; i < NC; i += TPB) {
            unsigned int v = s_cnt[i];
            if (v) red_u32(&g_icnt[i], v);
        }
    }

    grid_barrier(&g_bar1);

    // ---- Idle blocks: wait for all gathers, then zero accumulators ----
    if (bid >= MLPB) {
        __shared__ unsigned int s_target;
        if (t == 0) {
            unsigned int tk = atomicAdd(&g_arr, 1u);      // own arrival
            s_target = (tk / GRID + 1u) * GRID;
        }
        __syncthreads();
        if (t == 0) {
            unsigned int v;
            do {
                asm volatile("ld.acquire.gpu.u32 %0, [%1];" : "=r"(v) : "l"(&g_arr));
            } while (v < s_target);
        }
        __syncthreads();
        // All 296 blocks have finished reading g_rsum/g_icnt: re-zero them.
        const int zb = bid - MLPB;                        // 0..45
        for (int i = zb * TPB + t; i < NC * NREP * 2; i += 46 * TPB)
            g_rsum[i] = make_float4(0.f, 0.f, 0.f, 0.f);
        for (int i = zb * TPB + t; i < NC; i += 46 * TPB)
            g_icnt[i] = 0u;
        return;
    }

    // ---- Phase 2: edge MLP (blocks 0..249, 64 edges each) ----
    float* s_W1   = s_misc;          // 512 floats [4][128]  (hist is dead)
    float* s_b1   = s_misc + 512;    // 128
    float* s_b2   = s_misc + 640;    // 64
    float* s_pool = s_misc + 704;    // 320 floats [64][5]

    __syncthreads();
    if (t < 128) ((float4*)s_W1)[t] = ((const float4*)W1)[t];
    if (t < 128) s_b1[t] = b1[t];
    if (t < 64)  s_b2[t] = b2[t];

    const int base = bid * 64;

    // Gather: 4 threads/edge, each sums 2 padded replicas of both endpoints
    // (4 pipelined LDG.128 from warm L2), 2-step shfl reduce.
    {
        int q = t & 3;
        int e = t >> 2;
        int eg = base + e;
        int a = __ldg(eidx + eg);
        int b = __ldg(eidx + NE + eg);

        const float4* ra = g_rsum + a * (NREP * 2) + q * 4;
        const float4* rb = g_rsum + b * (NREP * 2) + q * 4;
        float4 va0 = __ldg(ra + 0);
        float4 va1 = __ldg(ra + 2);
        float4 vb0 = __ldg(rb + 0);
        float4 vb1 = __ldg(rb + 2);
        float4 s = make_float4(va0.x + va1.x + vb0.x + vb1.x,
                               va0.y + va1.y + vb0.y + vb1.y,
                               va0.z + va1.z + vb0.z + vb1.z,
                               va0.w + va1.w + vb0.w + vb1.w);
#pragma unroll
        for (int off = 2; off > 0; off >>= 1) {
            s.x += __shfl_down_sync(0xffffffff, s.x, off);
            s.y += __shfl_down_sync(0xffffffff, s.y, off);
            s.z += __shfl_down_sync(0xffffffff, s.z, off);
            s.w += __shfl_down_sync(0xffffffff, s.w, off);
        }
        if (q == 0) {
            float cnt = (float)(__ldg(g_icnt + a) + __ldg(g_icnt + b));
            float inv = 1.f / fmaxf(cnt, 1.f);
            s_pool[e * 5 + 0] = s.x * inv;
            s_pool[e * 5 + 1] = s.y * inv;
            s_pool[e * 5 + 2] = s.z * inv;
            s_pool[e * 5 + 3] = s.w * inv;
        }
    }
    __syncthreads();                 // gather loads complete block-wide

    // Non-blocking arrival: this block is done reading g_rsum/g_icnt.
    if (t == 0) atomicAdd(&g_arr, 1u);

    // Phase A: e = t&63, k-group kq = (t>>6)*32.
    {
        int e  = t & 63;
        int kq = (t >> 6) * 32;
        float p0 = s_pool[e * 5 + 0];
        float p1 = s_pool[e * 5 + 1];
        float p2 = s_pool[e * 5 + 2];
        float p3 = s_pool[e * 5 + 3];
#pragma unroll 4
        for (int j = 0; j < 32; j++) {
            int k = kq + j;
            float h = s_b1[k]
                    + p0 * s_W1[0 * 128 + k]
                    + p1 * s_W1[1 * 128 + k]
                    + p2 * s_W1[2 * 128 + k]
                    + p3 * s_W1[3 * 128 + k];
            s_h[k * 64 + e] = fmaxf(h, 0.f);
        }
    }
    __syncthreads();

    // Phase B: 4 edges x 4 outs per thread, packed f32x2 accumulators.
    const int tx = t & 15;
    const int ty = t >> 4;
    unsigned long long acc[4][2];
#pragma unroll
    for (int i = 0; i < 4; i++) { acc[i][0] = 0ull; acc[i][1] = 0ull; }

    const float4* hf4 = (const float4*)s_h;    // [128][16]
    const float4* wf4 = (const float4*)s_W2;   // [128][16]
#pragma unroll 4
    for (int k = 0; k < 128; k++) {
        float4 w = wf4[k * 16 + tx];           // conflict-free
        float4 h = hf4[k * 16 + ty];           // broadcast
        unsigned long long w01 = pack2(w.x, w.y);
        unsigned long long w23 = pack2(w.z, w.w);
        float hv[4] = {h.x, h.y, h.z, h.w};
#pragma unroll
        for (int i = 0; i < 4; i++) {
            unsigned long long hh = pack2(hv[i], hv[i]);
            ffma2(acc[i][0], hh, w01);
            ffma2(acc[i][1], hh, w23);
        }
    }

    float c0 = s_b2[tx * 4 + 0];
    float c1 = s_b2[tx * 4 + 1];
    float c2 = s_b2[tx * 4 + 2];
    float c3 = s_b2[tx * 4 + 3];
#pragma unroll
    for (int i = 0; i < 4; i++) {
        int e = base + ty * 4 + i;
        float a0, a1, a2, a3;
        unpack2(acc[i][0], a0, a1);
        unpack2(acc[i][1], a2, a3);
        float4 o = make_float4(a0 + c0, a1 + c1, a2 + c2, a3 + c3);
        ((float4*)out)[e * 16 + tx] = o;
    }
}

// ---------------------------------------------------------------------------
// Launch: ONE kernel node (graph-capturable)
// ---------------------------------------------------------------------------
extern "C" void kernel_launch(void* const* d_in, const int* in_sizes, int n_in,
                              void* d_out, int out_size) {
    const float* data = (const float*)d_in[0];
    const int*   cid  = (const int*)  d_in[1];
    const int*   eidx = (const int*)  d_in[2];
    const float* W1   = (const float*)d_in[3];
    const float* b1   = (const float*)d_in[4];
    const float* W2   = (const float*)d_in[5];
    const float* b2   = (const float*)d_in[6];
    float*       out  = (float*)d_out;

    cudaFuncSetAttribute(k_fused, cudaFuncAttributeMaxDynamicSharedMemorySize, 73728);

    k_fused<<<GRID, TPB, 73728>>>(data, cid, eidx, W1, b1, W2, b2, out);
}